// round 2
// baseline (speedup 1.0000x reference)
#include <cuda_runtime.h>

#define N_IN    4096
#define N_NODES 2048
#define FAN     8
#define BATCH   8192
#define ROWS    4
#define TPB     256

// Precomputed per-node softmax weights and int32 indices (scratch: __device__ globals)
__device__ int   g_idx[N_NODES * FAN];
__device__ float g_p[N_NODES * FAN];

__device__ __forceinline__ float fexp2(float a) {
    float r; asm("ex2.approx.ftz.f32 %0, %1;" : "=f"(r) : "f"(a)); return r;
}
__device__ __forceinline__ float flog2(float a) {
    float r; asm("lg2.approx.ftz.f32 %0, %1;" : "=f"(r) : "f"(a)); return r;
}

// Kernel 1: p[n,k] = softmax(weights[n,:])[k]; idx -> int32 with dtype sniffing.
// JAX without x64 silently makes "int64" arrays int32 — detect which we got:
// for little-endian int64 with values in [0, 4096), every odd 32-bit word is 0.
__global__ void prep_kernel(const float* __restrict__ w,
                            const int* __restrict__ idx_raw) {
    int n = blockIdx.x * blockDim.x + threadIdx.x;
    if (n >= N_NODES) return;

    bool is64 = true;
#pragma unroll 4
    for (int i = 0; i < 64; i++) {
        if (idx_raw[2 * i + 1] != 0) { is64 = false; break; }
    }

#pragma unroll
    for (int k = 0; k < FAN; k++) {
        int v = is64 ? idx_raw[2 * (n * FAN + k)]   // low word of int64
                     : idx_raw[n * FAN + k];        // plain int32
        g_idx[n * FAN + k] = v;
    }

    const float L2E = 1.4426950408889634f;
    float wv[FAN];
#pragma unroll
    for (int k = 0; k < FAN; k++) wv[k] = w[n * FAN + k];

    float m = wv[0];
#pragma unroll
    for (int k = 1; k < FAN; k++) m = fmaxf(m, wv[k]);

    float e[FAN];
    float s = 0.0f;
#pragma unroll
    for (int k = 0; k < FAN; k++) { e[k] = fexp2((wv[k] - m) * L2E); s += e[k]; }

    float inv = 1.0f / s;
#pragma unroll
    for (int k = 0; k < FAN; k++) g_p[n * FAN + k] = e[k] * inv;
}

// Kernel 2: per block handle ROWS=4 batch rows.
// Phase 1: stage E[b0..b0+3][i] = e^x into smem as float4 per column i
//          (thread reads same column of 4 rows -> 4 coalesced LDG.32, 1 conflict-free STS.128).
// Phase 2: per node, 8x LDS.128 gathers feed 4 row-accumulators; 4x LG2 epilogue.
__global__ void __launch_bounds__(TPB)
sum_kernel(const float* __restrict__ x, float* __restrict__ out) {
    extern __shared__ float4 sE[];   // [N_IN] float4 = 64 KB
    const int   b0  = blockIdx.x * ROWS;
    const float L2E = 1.4426950408889634f;
    const float LN2 = 0.6931471805599453f;

    const float* xb = x + (size_t)b0 * N_IN;

    // Phase 1: build E tile
    for (int c = threadIdx.x; c < N_IN; c += TPB) {
        float4 v;
        v.x = fexp2(xb[0 * N_IN + c] * L2E);
        v.y = fexp2(xb[1 * N_IN + c] * L2E);
        v.z = fexp2(xb[2 * N_IN + c] * L2E);
        v.w = fexp2(xb[3 * N_IN + c] * L2E);
        sE[c] = v;
    }
    __syncthreads();

    // Phase 2: gather-FMA per node
    const int4*   gi  = (const int4*)g_idx;
    const float4* gpv = (const float4*)g_p;

    for (int n = threadIdx.x; n < N_NODES; n += TPB) {
        int4   ia = gi[2 * n + 0];
        int4   ib = gi[2 * n + 1];
        float4 pa = gpv[2 * n + 0];
        float4 pb = gpv[2 * n + 1];

        float ax = 0.f, ay = 0.f, az = 0.f, aw = 0.f;
        float4 e;

        e = sE[ia.x]; ax += pa.x * e.x; ay += pa.x * e.y; az += pa.x * e.z; aw += pa.x * e.w;
        e = sE[ia.y]; ax += pa.y * e.x; ay += pa.y * e.y; az += pa.y * e.z; aw += pa.y * e.w;
        e = sE[ia.z]; ax += pa.z * e.x; ay += pa.z * e.y; az += pa.z * e.z; aw += pa.z * e.w;
        e = sE[ia.w]; ax += pa.w * e.x; ay += pa.w * e.y; az += pa.w * e.z; aw += pa.w * e.w;
        e = sE[ib.x]; ax += pb.x * e.x; ay += pb.x * e.y; az += pb.x * e.z; aw += pb.x * e.w;
        e = sE[ib.y]; ax += pb.y * e.x; ay += pb.y * e.y; az += pb.y * e.z; aw += pb.y * e.w;
        e = sE[ib.z]; ax += pb.z * e.x; ay += pb.z * e.y; az += pb.z * e.z; aw += pb.z * e.w;
        e = sE[ib.w]; ax += pb.w * e.x; ay += pb.w * e.y; az += pb.w * e.z; aw += pb.w * e.w;

        float* o = out + (size_t)b0 * N_NODES + n;
        o[0 * N_NODES] = flog2(ax) * LN2;
        o[1 * N_NODES] = flog2(ay) * LN2;
        o[2 * N_NODES] = flog2(az) * LN2;
        o[3 * N_NODES] = flog2(aw) * LN2;
    }
}

extern "C" void kernel_launch(void* const* d_in, const int* in_sizes, int n_in,
                              void* d_out, int out_size) {
    const float* x   = (const float*)d_in[0];
    const float* w   = (const float*)d_in[1];
    const int*   idx = (const int*)d_in[2];
    float*       out = (float*)d_out;

    (void)in_sizes; (void)n_in; (void)out_size;

    // Opt-in to 64 KB dynamic smem (idempotent, executes immediately even under capture)
    cudaFuncSetAttribute(sum_kernel, cudaFuncAttributeMaxDynamicSharedMemorySize,
                         N_IN * ROWS * (int)sizeof(float));

    prep_kernel<<<(N_NODES + TPB - 1) / TPB, TPB>>>(w, idx);
    sum_kernel<<<BATCH / ROWS, TPB, N_IN * ROWS * sizeof(float)>>>(x, out);
}

// round 5
// speedup vs baseline: 1.2692x; 1.2692x over previous
#include <cuda_runtime.h>

#define N_IN    4096
#define N_NODES 2048
#define FAN     8
#define BATCH   8192
#define ROWS    4
#define TPB     512
#define PREP_TPB 256

// Precomputed per-node softmax weights and int32 indices (scratch: __device__ globals)
__device__ int   g_idx[N_NODES * FAN];
__device__ float g_p[N_NODES * FAN];

__device__ __forceinline__ float fexp2(float a) {
    float r; asm("ex2.approx.ftz.f32 %0, %1;" : "=f"(r) : "f"(a)); return r;
}
__device__ __forceinline__ float flog2(float a) {
    float r; asm("lg2.approx.ftz.f32 %0, %1;" : "=f"(r) : "f"(a)); return r;
}

// Kernel 1: p[n,k] = softmax(weights[n,:])[k]; idx -> int32 with dtype sniffing.
// JAX without x64 silently makes "int64" arrays int32 — detect which we got:
// for little-endian int64 with values in [0, 4096), every odd 32-bit word is 0.
__global__ void prep_kernel(const float* __restrict__ w,
                            const int* __restrict__ idx_raw) {
    int n = blockIdx.x * blockDim.x + threadIdx.x;
    if (n >= N_NODES) return;

    bool is64 = true;
#pragma unroll 4
    for (int i = 0; i < 64; i++) {
        if (idx_raw[2 * i + 1] != 0) { is64 = false; break; }
    }

#pragma unroll
    for (int k = 0; k < FAN; k++) {
        int v = is64 ? idx_raw[2 * (n * FAN + k)]   // low word of int64
                     : idx_raw[n * FAN + k];        // plain int32
        g_idx[n * FAN + k] = v;
    }

    const float L2E = 1.4426950408889634f;
    float wv[FAN];
#pragma unroll
    for (int k = 0; k < FAN; k++) wv[k] = w[n * FAN + k];

    float m = wv[0];
#pragma unroll
    for (int k = 1; k < FAN; k++) m = fmaxf(m, wv[k]);

    float e[FAN];
    float s = 0.0f;
#pragma unroll
    for (int k = 0; k < FAN; k++) { e[k] = fexp2((wv[k] - m) * L2E); s += e[k]; }

    float inv = 1.0f / s;
#pragma unroll
    for (int k = 0; k < FAN; k++) g_p[n * FAN + k] = e[k] * inv;
}

// Kernel 2: per block handle ROWS=4 batch rows, 512 threads, 3 CTAs/SM (75% occ).
// Phase 1: stage E[b0..b0+3][i] = e^x into smem as float4 per column i
//          (thread reads same column of 4 rows -> 4 coalesced LDG.32, 1 conflict-free STS.128).
// Phase 2: per node, 8x LDS.128 gathers feed 4 row-accumulators; 4x LG2 epilogue.
__global__ void __launch_bounds__(TPB, 3)
sum_kernel(const float* __restrict__ x, float* __restrict__ out) {
    extern __shared__ float4 sE[];   // [N_IN] float4 = 64 KB
    const int   b0  = blockIdx.x * ROWS;
    const float L2E = 1.4426950408889634f;
    const float LN2 = 0.6931471805599453f;

    const float* xb = x + (size_t)b0 * N_IN;

    // Phase 1: build E tile (4096 cols / 512 threads = 8 iters)
    for (int c = threadIdx.x; c < N_IN; c += TPB) {
        float4 v;
        v.x = fexp2(xb[0 * N_IN + c] * L2E);
        v.y = fexp2(xb[1 * N_IN + c] * L2E);
        v.z = fexp2(xb[2 * N_IN + c] * L2E);
        v.w = fexp2(xb[3 * N_IN + c] * L2E);
        sE[c] = v;
    }
    __syncthreads();

    // Phase 2: gather-FMA per node (2048 nodes / 512 threads = 4 iters)
    const int4*   gi  = (const int4*)g_idx;
    const float4* gpv = (const float4*)g_p;

    for (int n = threadIdx.x; n < N_NODES; n += TPB) {
        int4   ia = gi[2 * n + 0];
        int4   ib = gi[2 * n + 1];
        float4 pa = gpv[2 * n + 0];
        float4 pb = gpv[2 * n + 1];

        float ax = 0.f, ay = 0.f, az = 0.f, aw = 0.f;
        float4 e;

        e = sE[ia.x]; ax += pa.x * e.x; ay += pa.x * e.y; az += pa.x * e.z; aw += pa.x * e.w;
        e = sE[ia.y]; ax += pa.y * e.x; ay += pa.y * e.y; az += pa.y * e.z; aw += pa.y * e.w;
        e = sE[ia.z]; ax += pa.z * e.x; ay += pa.z * e.y; az += pa.z * e.z; aw += pa.z * e.w;
        e = sE[ia.w]; ax += pa.w * e.x; ay += pa.w * e.y; az += pa.w * e.z; aw += pa.w * e.w;
        e = sE[ib.x]; ax += pb.x * e.x; ay += pb.x * e.y; az += pb.x * e.z; aw += pb.x * e.w;
        e = sE[ib.y]; ax += pb.y * e.x; ay += pb.y * e.y; az += pb.y * e.z; aw += pb.y * e.w;
        e = sE[ib.z]; ax += pb.z * e.x; ay += pb.z * e.y; az += pb.z * e.z; aw += pb.z * e.w;
        e = sE[ib.w]; ax += pb.w * e.x; ay += pb.w * e.y; az += pb.w * e.z; aw += pb.w * e.w;

        float* o = out + (size_t)b0 * N_NODES + n;
        o[0 * N_NODES] = flog2(ax) * LN2;
        o[1 * N_NODES] = flog2(ay) * LN2;
        o[2 * N_NODES] = flog2(az) * LN2;
        o[3 * N_NODES] = flog2(aw) * LN2;
    }
}

extern "C" void kernel_launch(void* const* d_in, const int* in_sizes, int n_in,
                              void* d_out, int out_size) {
    const float* x   = (const float*)d_in[0];
    const float* w   = (const float*)d_in[1];
    const int*   idx = (const int*)d_in[2];
    float*       out = (float*)d_out;

    (void)in_sizes; (void)n_in; (void)out_size;

    // Opt-in to 64 KB dynamic smem (idempotent, executes immediately even under capture)
    cudaFuncSetAttribute(sum_kernel, cudaFuncAttributeMaxDynamicSharedMemorySize,
                         N_IN * ROWS * (int)sizeof(float));

    prep_kernel<<<(N_NODES + PREP_TPB - 1) / PREP_TPB, PREP_TPB>>>(w, idx);
    sum_kernel<<<BATCH / ROWS, TPB, N_IN * ROWS * sizeof(float)>>>(x, out);
}

// round 6
// speedup vs baseline: 1.6827x; 1.3258x over previous
#include <cuda_runtime.h>
#include <cuda_fp16.h>

#define N_IN    4096
#define N_NODES 2048
#define FAN     8
#define BATCH   8192
#define ROWS    4
#define TPB     512
#define PREP_TPB 256

// Precomputed per-node softmax weights and int32 indices (scratch: __device__ globals)
__device__ int   g_idx[N_NODES * FAN];
__device__ float g_p[N_NODES * FAN];

__device__ __forceinline__ float fexp2(float a) {
    float r; asm("ex2.approx.ftz.f32 %0, %1;" : "=f"(r) : "f"(a)); return r;
}
__device__ __forceinline__ float flog2(float a) {
    float r; asm("lg2.approx.ftz.f32 %0, %1;" : "=f"(r) : "f"(a)); return r;
}

// Kernel 1: p[n,k] = softmax(weights[n,:])[k]; idx -> int32 with dtype sniffing.
// JAX without x64 silently makes "int64" arrays int32 — detect which we got:
// for little-endian int64 with values in [0, 4096), every odd 32-bit word is 0.
__global__ void prep_kernel(const float* __restrict__ w,
                            const int* __restrict__ idx_raw) {
    int n = blockIdx.x * blockDim.x + threadIdx.x;
    if (n >= N_NODES) return;

    bool is64 = true;
#pragma unroll 4
    for (int i = 0; i < 64; i++) {
        if (idx_raw[2 * i + 1] != 0) { is64 = false; break; }
    }

#pragma unroll
    for (int k = 0; k < FAN; k++) {
        int v = is64 ? idx_raw[2 * (n * FAN + k)]   // low word of int64
                     : idx_raw[n * FAN + k];        // plain int32
        g_idx[n * FAN + k] = v;
    }

    const float L2E = 1.4426950408889634f;
    float wv[FAN];
#pragma unroll
    for (int k = 0; k < FAN; k++) wv[k] = w[n * FAN + k];

    float m = wv[0];
#pragma unroll
    for (int k = 1; k < FAN; k++) m = fmaxf(m, wv[k]);

    float e[FAN];
    float s = 0.0f;
#pragma unroll
    for (int k = 0; k < FAN; k++) { e[k] = fexp2((wv[k] - m) * L2E); s += e[k]; }

    float inv = 1.0f / s;
#pragma unroll
    for (int k = 0; k < FAN; k++) g_p[n * FAN + k] = e[k] * inv;
}

// Kernel 2: per block handle ROWS=4 batch rows, 512 threads, 4 CTAs/SM (100% occ).
// E tile stored as fp16: column i -> uint2{half2(r0,r1), half2(r2,r3)} = 8B.
// Phase 1: 4 coalesced LDG.32 per column, fp32 ex2, pack to half4, STS.64 (conflict-free).
// Phase 2: per node, 8x LDS.64 gathers (half the bytes/conflicts of fp32), fp32 FMA accum,
//          4x LG2 epilogue. Gathers split into two halves of 4 to cap register pressure.
__global__ void __launch_bounds__(TPB, 4)
sum_kernel(const float* __restrict__ x, float* __restrict__ out) {
    extern __shared__ uint2 sE[];   // [N_IN] half4 = 32 KB
    const int   b0  = blockIdx.x * ROWS;
    const float L2E = 1.4426950408889634f;
    const float LN2 = 0.6931471805599453f;

    const float* xb = x + (size_t)b0 * N_IN;

    // Phase 1: build E tile (4096 cols / 512 threads = 8 iters)
    for (int c = threadIdx.x; c < N_IN; c += TPB) {
        float v0 = fexp2(xb[0 * N_IN + c] * L2E);
        float v1 = fexp2(xb[1 * N_IN + c] * L2E);
        float v2 = fexp2(xb[2 * N_IN + c] * L2E);
        float v3 = fexp2(xb[3 * N_IN + c] * L2E);
        __half2 h01 = __floats2half2_rn(v0, v1);
        __half2 h23 = __floats2half2_rn(v2, v3);
        uint2 packed;
        packed.x = *(const unsigned int*)&h01;
        packed.y = *(const unsigned int*)&h23;
        sE[c] = packed;
    }
    __syncthreads();

    // Phase 2: gather-FMA per node (2048 nodes / 512 threads = 4 iters)
    const int4*   gi  = (const int4*)g_idx;
    const float4* gpv = (const float4*)g_p;

    for (int n = threadIdx.x; n < N_NODES; n += TPB) {
        float ax = 0.f, ay = 0.f, az = 0.f, aw = 0.f;

        {
            int4   ia = gi[2 * n + 0];
            float4 pa = gpv[2 * n + 0];
            uint2 e; float2 f01, f23;
            e = sE[ia.x]; f01 = __half22float2(*(__half2*)&e.x); f23 = __half22float2(*(__half2*)&e.y);
            ax += pa.x * f01.x; ay += pa.x * f01.y; az += pa.x * f23.x; aw += pa.x * f23.y;
            e = sE[ia.y]; f01 = __half22float2(*(__half2*)&e.x); f23 = __half22float2(*(__half2*)&e.y);
            ax += pa.y * f01.x; ay += pa.y * f01.y; az += pa.y * f23.x; aw += pa.y * f23.y;
            e = sE[ia.z]; f01 = __half22float2(*(__half2*)&e.x); f23 = __half22float2(*(__half2*)&e.y);
            ax += pa.z * f01.x; ay += pa.z * f01.y; az += pa.z * f23.x; aw += pa.z * f23.y;
            e = sE[ia.w]; f01 = __half22float2(*(__half2*)&e.x); f23 = __half22float2(*(__half2*)&e.y);
            ax += pa.w * f01.x; ay += pa.w * f01.y; az += pa.w * f23.x; aw += pa.w * f23.y;
        }
        {
            int4   ib = gi[2 * n + 1];
            float4 pb = gpv[2 * n + 1];
            uint2 e; float2 f01, f23;
            e = sE[ib.x]; f01 = __half22float2(*(__half2*)&e.x); f23 = __half22float2(*(__half2*)&e.y);
            ax += pb.x * f01.x; ay += pb.x * f01.y; az += pb.x * f23.x; aw += pb.x * f23.y;
            e = sE[ib.y]; f01 = __half22float2(*(__half2*)&e.x); f23 = __half22float2(*(__half2*)&e.y);
            ax += pb.y * f01.x; ay += pb.y * f01.y; az += pb.y * f23.x; aw += pb.y * f23.y;
            e = sE[ib.z]; f01 = __half22float2(*(__half2*)&e.x); f23 = __half22float2(*(__half2*)&e.y);
            ax += pb.z * f01.x; ay += pb.z * f01.y; az += pb.z * f23.x; aw += pb.z * f23.y;
            e = sE[ib.w]; f01 = __half22float2(*(__half2*)&e.x); f23 = __half22float2(*(__half2*)&e.y);
            ax += pb.w * f01.x; ay += pb.w * f01.y; az += pb.w * f23.x; aw += pb.w * f23.y;
        }

        float* o = out + (size_t)b0 * N_NODES + n;
        o[0 * N_NODES] = flog2(ax) * LN2;
        o[1 * N_NODES] = flog2(ay) * LN2;
        o[2 * N_NODES] = flog2(az) * LN2;
        o[3 * N_NODES] = flog2(aw) * LN2;
    }
}

extern "C" void kernel_launch(void* const* d_in, const int* in_sizes, int n_in,
                              void* d_out, int out_size) {
    const float* x   = (const float*)d_in[0];
    const float* w   = (const float*)d_in[1];
    const int*   idx = (const int*)d_in[2];
    float*       out = (float*)d_out;

    (void)in_sizes; (void)n_in; (void)out_size;

    prep_kernel<<<(N_NODES + PREP_TPB - 1) / PREP_TPB, PREP_TPB>>>(w, idx);
    sum_kernel<<<BATCH / ROWS, TPB, N_IN * (int)sizeof(uint2)>>>(x, out);
}

// round 7
// speedup vs baseline: 1.7785x; 1.0569x over previous
#include <cuda_runtime.h>
#include <cuda_fp16.h>

#define N_IN    4096
#define N_NODES 2048
#define FAN     8
#define BATCH   8192
#define ROWS    8
#define TPB     512
#define PREP_TPB 256

// Precomputed per-node softmax weights and int32 indices (scratch: __device__ globals)
__device__ int   g_idx[N_NODES * FAN];
__device__ float g_p[N_NODES * FAN];

__device__ __forceinline__ float fexp2(float a) {
    float r; asm("ex2.approx.ftz.f32 %0, %1;" : "=f"(r) : "f"(a)); return r;
}
__device__ __forceinline__ float flog2(float a) {
    float r; asm("lg2.approx.ftz.f32 %0, %1;" : "=f"(r) : "f"(a)); return r;
}

// Kernel 1: p[n,k] = softmax(weights[n,:])[k]; idx -> int32 with dtype sniffing.
// JAX without x64 silently makes "int64" arrays int32 — detect which we got:
// for little-endian int64 with values in [0, 4096), every odd 32-bit word is 0.
__global__ void prep_kernel(const float* __restrict__ w,
                            const int* __restrict__ idx_raw) {
    int n = blockIdx.x * blockDim.x + threadIdx.x;
    if (n >= N_NODES) return;

    bool is64 = true;
#pragma unroll 4
    for (int i = 0; i < 64; i++) {
        if (idx_raw[2 * i + 1] != 0) { is64 = false; break; }
    }

#pragma unroll
    for (int k = 0; k < FAN; k++) {
        int v = is64 ? idx_raw[2 * (n * FAN + k)]   // low word of int64
                     : idx_raw[n * FAN + k];        // plain int32
        g_idx[n * FAN + k] = v;
    }

    const float L2E = 1.4426950408889634f;
    float wv[FAN];
#pragma unroll
    for (int k = 0; k < FAN; k++) wv[k] = w[n * FAN + k];

    float m = wv[0];
#pragma unroll
    for (int k = 1; k < FAN; k++) m = fmaxf(m, wv[k]);

    float e[FAN];
    float s = 0.0f;
#pragma unroll
    for (int k = 0; k < FAN; k++) { e[k] = fexp2((wv[k] - m) * L2E); s += e[k]; }

    float inv = 1.0f / s;
#pragma unroll
    for (int k = 0; k < FAN; k++) g_p[n * FAN + k] = e[k] * inv;
}

// One FMA-accumulate of a gathered half8 column scaled by p into 8 row-accumulators.
#define GATHER_ACC(IDX, P)                                                     \
    do {                                                                       \
        uint4 e = sE[(IDX)];                                                   \
        float2 f;                                                              \
        f = __half22float2(*(__half2*)&e.x); a0 += (P) * f.x; a1 += (P) * f.y; \
        f = __half22float2(*(__half2*)&e.y); a2 += (P) * f.x; a3 += (P) * f.y; \
        f = __half22float2(*(__half2*)&e.z); a4 += (P) * f.x; a5 += (P) * f.y; \
        f = __half22float2(*(__half2*)&e.w); a6 += (P) * f.x; a7 += (P) * f.y; \
    } while (0)

// Kernel 2: per block handle ROWS=8 batch rows, 512 threads, 3 CTAs/SM (75% occ).
// E tile as fp16: column i -> uint4 of 4x half2 = 16B covering 8 rows.
// Phase 1: 8 coalesced LDG.32 per column, 8x ex2, pack, STS.128 (conflict-free).
// Phase 2: per node, 8x LDS.128 gathers (16B serves 8 output rows; conflict
//          positions are 16B quads -> fewer independent bank picks than LDS.64),
//          fp32 FMA accum into 8 registers, 8x LG2 epilogue, coalesced STG.
__global__ void __launch_bounds__(TPB, 3)
sum_kernel(const float* __restrict__ x, float* __restrict__ out) {
    extern __shared__ uint4 sE[];   // [N_IN] half8 = 64 KB
    const int   b0  = blockIdx.x * ROWS;
    const float L2E = 1.4426950408889634f;
    const float LN2 = 0.6931471805599453f;

    const float* xb = x + (size_t)b0 * N_IN;

    // Phase 1: build E tile (4096 cols / 512 threads = 8 iters)
    for (int c = threadIdx.x; c < N_IN; c += TPB) {
        float v0 = fexp2(xb[0 * N_IN + c] * L2E);
        float v1 = fexp2(xb[1 * N_IN + c] * L2E);
        float v2 = fexp2(xb[2 * N_IN + c] * L2E);
        float v3 = fexp2(xb[3 * N_IN + c] * L2E);
        float v4 = fexp2(xb[4 * N_IN + c] * L2E);
        float v5 = fexp2(xb[5 * N_IN + c] * L2E);
        float v6 = fexp2(xb[6 * N_IN + c] * L2E);
        float v7 = fexp2(xb[7 * N_IN + c] * L2E);
        __half2 h01 = __floats2half2_rn(v0, v1);
        __half2 h23 = __floats2half2_rn(v2, v3);
        __half2 h45 = __floats2half2_rn(v4, v5);
        __half2 h67 = __floats2half2_rn(v6, v7);
        uint4 packed;
        packed.x = *(const unsigned int*)&h01;
        packed.y = *(const unsigned int*)&h23;
        packed.z = *(const unsigned int*)&h45;
        packed.w = *(const unsigned int*)&h67;
        sE[c] = packed;
    }
    __syncthreads();

    // Phase 2: gather-FMA per node (2048 nodes / 512 threads = 4 iters)
    const int4*   gi  = (const int4*)g_idx;
    const float4* gpv = (const float4*)g_p;

    for (int n = threadIdx.x; n < N_NODES; n += TPB) {
        float a0 = 0.f, a1 = 0.f, a2 = 0.f, a3 = 0.f;
        float a4 = 0.f, a5 = 0.f, a6 = 0.f, a7 = 0.f;

        {
            int4   ia = gi[2 * n + 0];
            float4 pa = gpv[2 * n + 0];
            GATHER_ACC(ia.x, pa.x);
            GATHER_ACC(ia.y, pa.y);
            GATHER_ACC(ia.z, pa.z);
            GATHER_ACC(ia.w, pa.w);
        }
        {
            int4   ib = gi[2 * n + 1];
            float4 pb = gpv[2 * n + 1];
            GATHER_ACC(ib.x, pb.x);
            GATHER_ACC(ib.y, pb.y);
            GATHER_ACC(ib.z, pb.z);
            GATHER_ACC(ib.w, pb.w);
        }

        float* o = out + (size_t)b0 * N_NODES + n;
        o[0 * N_NODES] = flog2(a0) * LN2;
        o[1 * N_NODES] = flog2(a1) * LN2;
        o[2 * N_NODES] = flog2(a2) * LN2;
        o[3 * N_NODES] = flog2(a3) * LN2;
        o[4 * N_NODES] = flog2(a4) * LN2;
        o[5 * N_NODES] = flog2(a5) * LN2;
        o[6 * N_NODES] = flog2(a6) * LN2;
        o[7 * N_NODES] = flog2(a7) * LN2;
    }
}

extern "C" void kernel_launch(void* const* d_in, const int* in_sizes, int n_in,
                              void* d_out, int out_size) {
    const float* x   = (const float*)d_in[0];
    const float* w   = (const float*)d_in[1];
    const int*   idx = (const int*)d_in[2];
    float*       out = (float*)d_out;

    (void)in_sizes; (void)n_in; (void)out_size;

    // 64 KB dynamic smem needs an explicit opt-in (idempotent, capture-safe)
    cudaFuncSetAttribute(sum_kernel, cudaFuncAttributeMaxDynamicSharedMemorySize,
                         N_IN * (int)sizeof(uint4));

    prep_kernel<<<(N_NODES + PREP_TPB - 1) / PREP_TPB, PREP_TPB>>>(w, idx);
    sum_kernel<<<BATCH / ROWS, TPB, N_IN * (int)sizeof(uint4)>>>(x, out);
}

// round 8
// speedup vs baseline: 1.9512x; 1.0971x over previous
#include <cuda_runtime.h>
#include <cuda_fp16.h>

#define N_IN    4096
#define N_NODES 2048
#define FAN     8
#define BATCH   8192
#define ROWS    8
#define TPB     512

__device__ __forceinline__ float fexp2(float a) {
    float r; asm("ex2.approx.ftz.f32 %0, %1;" : "=f"(r) : "f"(a)); return r;
}
__device__ __forceinline__ float flog2(float a) {
    float r; asm("lg2.approx.ftz.f32 %0, %1;" : "=f"(r) : "f"(a)); return r;
}

// Gather child IDX (half8 column = 8 batch rows) and accumulate with unnormalized
// softmax weight s = e^{w-m}; S accumulates the normalizer.
#define CHILD(IDX, W)                                                              \
    do {                                                                           \
        float s_ = fexp2(((W) - m) * L2E);                                         \
        uint4 e_ = sE[(IDX)];                                                      \
        S += s_;                                                                   \
        float2 f_;                                                                 \
        f_ = __half22float2(*(__half2*)&e_.x); a0 += s_ * f_.x; a1 += s_ * f_.y;   \
        f_ = __half22float2(*(__half2*)&e_.y); a2 += s_ * f_.x; a3 += s_ * f_.y;   \
        f_ = __half22float2(*(__half2*)&e_.z); a4 += s_ * f_.x; a5 += s_ * f_.y;   \
        f_ = __half22float2(*(__half2*)&e_.w); a6 += s_ * f_.x; a7 += s_ * f_.y;   \
    } while (0)

// Single fused kernel. Per block: 8 batch rows, 512 threads, 3 CTAs/SM.
// Phase 1: E[8 rows][i] = e^x staged to smem as half8 columns (16B, STS.128
//          conflict-free); warp 0 simultaneously dtype-sniffs the idx buffer
//          (JAX x64-off silently makes "int64" int32 — for true int64 with
//          values <4096 every odd 32-bit word is 0; ballot over 64 words).
// Phase 2: per node, load raw w (32B) + raw idx (stream as int4), compute
//          softmax inline via the log identity:
//          lls = ln(sum_k e^{w_k-m} E_k) - ln(sum_k e^{w_k-m}).
//          8x LDS.128 gathers, fp32 accum, 9x LG2 epilogue, coalesced STG.
__global__ void __launch_bounds__(TPB, 3)
sum_kernel(const float* __restrict__ x, const float* __restrict__ w,
           const int* __restrict__ idx_raw, float* __restrict__ out) {
    extern __shared__ uint4 sE[];   // [N_IN] half8 = 64 KB
    __shared__ int s_is64;
    const int   b0  = blockIdx.x * ROWS;
    const float L2E = 1.4426950408889634f;
    const float LN2 = 0.6931471805599453f;

    // Dtype sniff (warp 0, overlapped with phase 1 of other warps)
    if (threadIdx.x < 32) {
        int l  = threadIdx.x;
        int v1 = idx_raw[2 * l + 1];
        int v2 = idx_raw[2 * (l + 32) + 1];
        unsigned nz = __ballot_sync(0xffffffffu, (v1 | v2) != 0);
        if (l == 0) s_is64 = (nz == 0);
    }

    const float* xb = x + (size_t)b0 * N_IN;

    // Phase 1: build E tile (4096 cols / 512 threads = 8 iters)
    for (int c = threadIdx.x; c < N_IN; c += TPB) {
        float v0 = fexp2(xb[0 * N_IN + c] * L2E);
        float v1 = fexp2(xb[1 * N_IN + c] * L2E);
        float v2 = fexp2(xb[2 * N_IN + c] * L2E);
        float v3 = fexp2(xb[3 * N_IN + c] * L2E);
        float v4 = fexp2(xb[4 * N_IN + c] * L2E);
        float v5 = fexp2(xb[5 * N_IN + c] * L2E);
        float v6 = fexp2(xb[6 * N_IN + c] * L2E);
        float v7 = fexp2(xb[7 * N_IN + c] * L2E);
        __half2 h01 = __floats2half2_rn(v0, v1);
        __half2 h23 = __floats2half2_rn(v2, v3);
        __half2 h45 = __floats2half2_rn(v4, v5);
        __half2 h67 = __floats2half2_rn(v6, v7);
        uint4 packed;
        packed.x = *(const unsigned int*)&h01;
        packed.y = *(const unsigned int*)&h23;
        packed.z = *(const unsigned int*)&h45;
        packed.w = *(const unsigned int*)&h67;
        sE[c] = packed;
    }
    __syncthreads();

    const bool is64 = (s_is64 != 0);

    // Phase 2: gather + inline softmax per node (2048 nodes / 512 threads = 4 iters)
    for (int n = threadIdx.x; n < N_NODES; n += TPB) {
        const float4* wv = (const float4*)(w + (size_t)n * FAN);
        float4 wa = wv[0];
        float4 wb = wv[1];

        float m = fmaxf(fmaxf(fmaxf(wa.x, wa.y), fmaxf(wa.z, wa.w)),
                        fmaxf(fmaxf(wb.x, wb.y), fmaxf(wb.z, wb.w)));

        float a0 = 0.f, a1 = 0.f, a2 = 0.f, a3 = 0.f;
        float a4 = 0.f, a5 = 0.f, a6 = 0.f, a7 = 0.f;
        float S  = 0.f;

        if (is64) {
            const int4* ip = (const int4*)idx_raw + (size_t)n * 4;  // 4x int4 = 8 int64
            int4 q;
            q = ip[0]; CHILD(q.x, wa.x); CHILD(q.z, wa.y);
            q = ip[1]; CHILD(q.x, wa.z); CHILD(q.z, wa.w);
            q = ip[2]; CHILD(q.x, wb.x); CHILD(q.z, wb.y);
            q = ip[3]; CHILD(q.x, wb.z); CHILD(q.z, wb.w);
        } else {
            const int4* ip = (const int4*)idx_raw + (size_t)n * 2;  // 2x int4 = 8 int32
            int4 q;
            q = ip[0]; CHILD(q.x, wa.x); CHILD(q.y, wa.y); CHILD(q.z, wa.z); CHILD(q.w, wa.w);
            q = ip[1]; CHILD(q.x, wb.x); CHILD(q.y, wb.y); CHILD(q.z, wb.z); CHILD(q.w, wb.w);
        }

        float c = flog2(S) * LN2;   // ln(normalizer)
        float* o = out + (size_t)b0 * N_NODES + n;
        o[0 * N_NODES] = fmaf(flog2(a0), LN2, -c);
        o[1 * N_NODES] = fmaf(flog2(a1), LN2, -c);
        o[2 * N_NODES] = fmaf(flog2(a2), LN2, -c);
        o[3 * N_NODES] = fmaf(flog2(a3), LN2, -c);
        o[4 * N_NODES] = fmaf(flog2(a4), LN2, -c);
        o[5 * N_NODES] = fmaf(flog2(a5), LN2, -c);
        o[6 * N_NODES] = fmaf(flog2(a6), LN2, -c);
        o[7 * N_NODES] = fmaf(flog2(a7), LN2, -c);
    }
}

extern "C" void kernel_launch(void* const* d_in, const int* in_sizes, int n_in,
                              void* d_out, int out_size) {
    const float* x   = (const float*)d_in[0];
    const float* w   = (const float*)d_in[1];
    const int*   idx = (const int*)d_in[2];
    float*       out = (float*)d_out;

    (void)in_sizes; (void)n_in; (void)out_size;

    // 64 KB dynamic smem needs an explicit opt-in (idempotent, capture-safe)
    cudaFuncSetAttribute(sum_kernel, cudaFuncAttributeMaxDynamicSharedMemorySize,
                         N_IN * (int)sizeof(uint4));

    sum_kernel<<<BATCH / ROWS, TPB, N_IN * (int)sizeof(uint4)>>>(x, w, idx, out);
}

// round 9
// speedup vs baseline: 1.9521x; 1.0005x over previous
#include <cuda_runtime.h>
#include <cuda_fp16.h>

#define N_IN    4096
#define N_NODES 2048
#define FAN     8
#define BATCH   8192
#define ROWS    8
#define TPB     512

__device__ __forceinline__ float fexp2(float a) {
    float r; asm("ex2.approx.ftz.f32 %0, %1;" : "=f"(r) : "f"(a)); return r;
}
__device__ __forceinline__ float flog2(float a) {
    float r; asm("lg2.approx.ftz.f32 %0, %1;" : "=f"(r) : "f"(a)); return r;
}

// Consume one gathered half8 column E (8 batch rows) with scalar weight s.
#define ACC(E, Sc)                                                                 \
    do {                                                                           \
        float2 f_;                                                                 \
        f_ = __half22float2(*(__half2*)&(E).x); a0 += (Sc) * f_.x; a1 += (Sc) * f_.y; \
        f_ = __half22float2(*(__half2*)&(E).y); a2 += (Sc) * f_.x; a3 += (Sc) * f_.y; \
        f_ = __half22float2(*(__half2*)&(E).z); a4 += (Sc) * f_.x; a5 += (Sc) * f_.y; \
        f_ = __half22float2(*(__half2*)&(E).w); a6 += (Sc) * f_.x; a7 += (Sc) * f_.y; \
    } while (0)

// Process 4 children: batch the 4 random LDS.128 gathers up-front (MLP=4),
// compute the 4 softmax exp-weights in the LDS shadow, then consume.
#define QUAD(I0, I1, I2, I3, W0, W1, W2, W3)                                       \
    do {                                                                           \
        uint4 e0_ = sE[(I0)];                                                      \
        uint4 e1_ = sE[(I1)];                                                      \
        uint4 e2_ = sE[(I2)];                                                      \
        uint4 e3_ = sE[(I3)];                                                      \
        float s0_ = fexp2(((W0) - m) * L2E);                                       \
        float s1_ = fexp2(((W1) - m) * L2E);                                       \
        float s2_ = fexp2(((W2) - m) * L2E);                                       \
        float s3_ = fexp2(((W3) - m) * L2E);                                       \
        S += (s0_ + s1_) + (s2_ + s3_);                                            \
        ACC(e0_, s0_); ACC(e1_, s1_); ACC(e2_, s2_); ACC(e3_, s3_);                \
    } while (0)

// Single fused kernel. Per block: 8 batch rows, 512 threads, 3 CTAs/SM.
// Phase 1: E[8 rows][i] = e^x staged to smem as half8 columns (16B, STS.128
//          conflict-free); warp 0 simultaneously dtype-sniffs the idx buffer
//          (JAX x64-off silently makes "int64" int32 — for true int64 with
//          values <4096 every odd 32-bit word is 0; ballot over 64 words).
// Phase 2: per node, softmax inline via the log identity
//          lls = ln(sum_k e^{w_k-m} E_k) - ln(sum_k e^{w_k-m}),
//          with gathers batched 4-wide for latency overlap.
__global__ void __launch_bounds__(TPB, 3)
sum_kernel(const float* __restrict__ x, const float* __restrict__ w,
           const int* __restrict__ idx_raw, float* __restrict__ out) {
    extern __shared__ uint4 sE[];   // [N_IN] half8 = 64 KB
    __shared__ int s_is64;
    const int   b0  = blockIdx.x * ROWS;
    const float L2E = 1.4426950408889634f;
    const float LN2 = 0.6931471805599453f;

    // Dtype sniff (warp 0, overlapped with phase 1 of other warps)
    if (threadIdx.x < 32) {
        int l  = threadIdx.x;
        int v1 = idx_raw[2 * l + 1];
        int v2 = idx_raw[2 * (l + 32) + 1];
        unsigned nz = __ballot_sync(0xffffffffu, (v1 | v2) != 0);
        if (l == 0) s_is64 = (nz == 0);
    }

    const float* xb = x + (size_t)b0 * N_IN;

    // Phase 1: build E tile (4096 cols / 512 threads = 8 iters)
    for (int c = threadIdx.x; c < N_IN; c += TPB) {
        float v0 = fexp2(xb[0 * N_IN + c] * L2E);
        float v1 = fexp2(xb[1 * N_IN + c] * L2E);
        float v2 = fexp2(xb[2 * N_IN + c] * L2E);
        float v3 = fexp2(xb[3 * N_IN + c] * L2E);
        float v4 = fexp2(xb[4 * N_IN + c] * L2E);
        float v5 = fexp2(xb[5 * N_IN + c] * L2E);
        float v6 = fexp2(xb[6 * N_IN + c] * L2E);
        float v7 = fexp2(xb[7 * N_IN + c] * L2E);
        __half2 h01 = __floats2half2_rn(v0, v1);
        __half2 h23 = __floats2half2_rn(v2, v3);
        __half2 h45 = __floats2half2_rn(v4, v5);
        __half2 h67 = __floats2half2_rn(v6, v7);
        uint4 packed;
        packed.x = *(const unsigned int*)&h01;
        packed.y = *(const unsigned int*)&h23;
        packed.z = *(const unsigned int*)&h45;
        packed.w = *(const unsigned int*)&h67;
        sE[c] = packed;
    }
    __syncthreads();

    const bool is64 = (s_is64 != 0);

    // Phase 2: gather + inline softmax per node (2048 nodes / 512 threads = 4 iters)
    for (int n = threadIdx.x; n < N_NODES; n += TPB) {
        const float4* wv = (const float4*)(w + (size_t)n * FAN);
        float4 wa = wv[0];
        float4 wb = wv[1];

        float m = fmaxf(fmaxf(fmaxf(wa.x, wa.y), fmaxf(wa.z, wa.w)),
                        fmaxf(fmaxf(wb.x, wb.y), fmaxf(wb.z, wb.w)));

        float a0 = 0.f, a1 = 0.f, a2 = 0.f, a3 = 0.f;
        float a4 = 0.f, a5 = 0.f, a6 = 0.f, a7 = 0.f;
        float S  = 0.f;

        if (is64) {
            const int4* ip = (const int4*)idx_raw + (size_t)n * 4;  // 4x int4 = 8 int64
            int4 q0 = ip[0], q1 = ip[1];
            QUAD(q0.x, q0.z, q1.x, q1.z, wa.x, wa.y, wa.z, wa.w);
            int4 q2 = ip[2], q3 = ip[3];
            QUAD(q2.x, q2.z, q3.x, q3.z, wb.x, wb.y, wb.z, wb.w);
        } else {
            const int4* ip = (const int4*)idx_raw + (size_t)n * 2;  // 2x int4 = 8 int32
            int4 q0 = ip[0];
            QUAD(q0.x, q0.y, q0.z, q0.w, wa.x, wa.y, wa.z, wa.w);
            int4 q1 = ip[1];
            QUAD(q1.x, q1.y, q1.z, q1.w, wb.x, wb.y, wb.z, wb.w);
        }

        float c = flog2(S) * LN2;   // ln(normalizer)
        float* o = out + (size_t)b0 * N_NODES + n;
        o[0 * N_NODES] = fmaf(flog2(a0), LN2, -c);
        o[1 * N_NODES] = fmaf(flog2(a1), LN2, -c);
        o[2 * N_NODES] = fmaf(flog2(a2), LN2, -c);
        o[3 * N_NODES] = fmaf(flog2(a3), LN2, -c);
        o[4 * N_NODES] = fmaf(flog2(a4), LN2, -c);
        o[5 * N_NODES] = fmaf(flog2(a5), LN2, -c);
        o[6 * N_NODES] = fmaf(flog2(a6), LN2, -c);
        o[7 * N_NODES] = fmaf(flog2(a7), LN2, -c);
    }
}

extern "C" void kernel_launch(void* const* d_in, const int* in_sizes, int n_in,
                              void* d_out, int out_size) {
    const float* x   = (const float*)d_in[0];
    const float* w   = (const float*)d_in[1];
    const int*   idx = (const int*)d_in[2];
    float*       out = (float*)d_out;

    (void)in_sizes; (void)n_in; (void)out_size;

    // 64 KB dynamic smem needs an explicit opt-in (idempotent, capture-safe)
    cudaFuncSetAttribute(sum_kernel, cudaFuncAttributeMaxDynamicSharedMemorySize,
                         N_IN * (int)sizeof(uint4));

    sum_kernel<<<BATCH / ROWS, TPB, N_IN * (int)sizeof(uint4)>>>(x, w, idx, out);
}